// round 4
// baseline (speedup 1.0000x reference)
#include <cuda_runtime.h>
#include <cuda_bf16.h>
#include <cub/cub.cuh>

// ---------------- problem constants ----------------
#define BB 4
#define AA 10
#define LL 4096
#define NPROP (LL * AA)          // 40960 per batch
#define TOTAL (BB * NPROP)       // 163840
#define PRE_NMS 6000
#define POST_NMS 300
#define MWORDS 188               // ceil(6000/32)
#define NMS_THRESH_F 0.7f
#define MIN_SIZE_F 8.0f
#define FEAT_STRIDE 8
#define CLIP_MAX 32767.0f        // L*FEAT_STRIDE - 1

#define MASK_ROWS_PER_BLOCK 128

// ---------------- static device scratch (no allocations allowed) ----------------
__device__ float g_x1[TOTAL];
__device__ float g_x2[TOTAL];
__device__ float g_keys_in[TOTAL];
__device__ float g_keys_out[TOTAL];
__device__ int   g_vals_in[TOTAL];
__device__ int   g_vals_out[TOTAL];
__device__ int   g_seg_off[BB + 1] = {0, NPROP, 2 * NPROP, 3 * NPROP, 4 * NPROP};
__device__ unsigned char g_cub_temp[8 << 20];
__device__ float2 g_obox[BB * PRE_NMS];                    // sorted-order candidate boxes
__device__ unsigned g_mask[(size_t)BB * PRE_NMS * MWORDS]; // suppression bitmasks (upper tri)

__constant__ float c_scales[AA] = {2.f, 4.f, 5.f, 6.f, 8.f, 9.f, 10.f, 12.f, 14.f, 16.f};

// ---------------- kernel 1: decode proposals + scores ----------------
// Thread mapping: t = ((b*2A + a-group)*L + l) style, l fastest -> coalesced loads.
__global__ void compute_props(const float* __restrict__ scores_in,
                              const float* __restrict__ deltas_in) {
    int t = blockIdx.x * blockDim.x + threadIdx.x;
    if (t >= TOTAL) return;
    int l = t & (LL - 1);              // LL = 4096, power of 2
    int ba = t >> 12;                  // b*AA + a
    int b = ba / AA;
    int a = ba - b * AA;

    const int base = b * (2 * AA) * LL;
    float score = scores_in[base + (AA + a) * LL + l];          // coalesced in l
    float d0    = deltas_in[base + (2 * a) * LL + l];           // coalesced in l
    float d1    = deltas_in[base + (2 * a + 1) * LL + l];       // coalesced in l

    float ws   = c_scales[a] * (float)FEAT_STRIDE;
    float ctrA = ((float)FEAT_STRIDE - 1.0f) * 0.5f;            // 3.5
    float shift = (float)(l * FEAT_STRIDE);
    float x1a = ctrA - 0.5f * (ws - 1.0f) + shift;
    float x2a = ctrA + 0.5f * (ws - 1.0f) + shift;

    float width = x2a - x1a + 1.0f;
    float ctr   = x1a + 0.5f * width;

    float pred_ctr = d0 * width + ctr;
    float pred_l   = expf(d1) * width;

    float x1 = pred_ctr - 0.5f * pred_l;
    float x2 = pred_ctr + 0.5f * pred_l;
    x1 = fminf(fmaxf(x1, 0.0f), CLIP_MAX);
    x2 = fminf(fmaxf(x2, 0.0f), CLIP_MAX);

    float ls = x2 - x1 + 1.0f;
    if (ls < MIN_SIZE_F) score = 0.0f;

    int r = l * AA + a;                // within-batch proposal index (reference order)
    int idx = b * NPROP + r;
    g_x1[idx] = x1;
    g_x2[idx] = x2;
    g_keys_in[idx] = score;
    g_vals_in[idx] = r;
}

// ---------------- kernel 2b: gather top-PRE_NMS boxes in sorted order ----------------
__global__ void gather_kernel() {
    int t = blockIdx.x * blockDim.x + threadIdx.x;
    if (t >= BB * PRE_NMS) return;
    int b = t / PRE_NMS;
    int i = t - b * PRE_NMS;
    int gi = b * NPROP + g_vals_out[b * NPROP + i];
    g_obox[t] = make_float2(g_x1[gi], g_x2[gi]);
}

// ---------------- kernel 3: pairwise suppression bitmask ----------------
// One row i per THREAD; all lanes sweep the same j -> smem broadcast (no conflicts).
// Only upper-triangle words (w >= i>>5) are computed/written.
__global__ void mask_kernel() {
    __shared__ float2 jb[PRE_NMS];   // 48000 B
    const int b = blockIdx.y;
    const int i = blockIdx.x * MASK_ROWS_PER_BLOCK + threadIdx.x;

    const float2* obox = g_obox + b * PRE_NMS;
    for (int j = threadIdx.x; j < PRE_NMS; j += blockDim.x)
        jb[j] = obox[j];
    __syncthreads();

    if (i >= PRE_NMS) return;

    const float2 bi = jb[i];
    const float leni = bi.y - bi.x + 1.0f;
    unsigned* mrow = g_mask + ((size_t)b * PRE_NMS + i) * MWORDS;

    const int w0 = i >> 5;
    for (int w = w0; w < MWORDS; ++w) {
        const int jbase = w << 5;
        int kmax = PRE_NMS - jbase; if (kmax > 32) kmax = 32;
        unsigned word = 0u;
        #pragma unroll 4
        for (int k = 0; k < kmax; ++k) {
            const int j = jbase + k;
            const float2 bj = jb[j];           // broadcast across warp
            float inter = fminf(bi.y, bj.y) - fmaxf(bi.x, bj.x) + 1.0f;
            if (j > i && inter > 0.0f) {
                float uni = leni + (bj.y - bj.x + 1.0f) - inter;
                if (inter / uni > NMS_THRESH_F) word |= (1u << k);
            }
        }
        mrow[w] = word;
    }
}

// ---------------- kernel 4: serial greedy resolve (1 warp per batch) ----------------
__global__ void resolve_kernel(float* __restrict__ out) {
    __shared__ unsigned s_remv[MWORDS];
    const int b = blockIdx.x;
    const int lane = threadIdx.x;      // 32 threads

    for (int w = lane; w < MWORDS; w += 32) s_remv[w] = 0u;
    for (int i = lane; i < POST_NMS; i += 32) {
        float* o = out + (b * POST_NMS + i) * 3;
        o[0] = (float)b; o[1] = 0.0f; o[2] = 0.0f;
    }
    __syncwarp();

    const unsigned* mask = g_mask + (size_t)b * PRE_NMS * MWORDS;
    const float2* obox = g_obox + b * PRE_NMS;

    int kept = 0;
    for (int w = 0; w < MWORDS && kept < POST_NMS; ++w) {
        unsigned valid = (w == MWORDS - 1) ? 0xFFFFu : 0xFFFFFFFFu;
        unsigned alive = (~s_remv[w]) & valid;
        while (alive && kept < POST_NMS) {
            int k = __ffs(alive) - 1;
            int i = w * 32 + k;        // first alive bit is always kept
            if (lane == 0) {
                float2 bx = obox[i];
                float* o = out + (b * POST_NMS + kept) * 3;
                o[1] = bx.x; o[2] = bx.y;
            }
            kept++;
            const unsigned* row = mask + (size_t)i * MWORDS;
            for (int ww = w + lane; ww < MWORDS; ww += 32) {
                unsigned m = row[ww];
                if (m) s_remv[ww] |= m;   // each word owned by one lane
            }
            __syncwarp();
            alive = (~s_remv[w]) & valid & ~((2u << k) - 1u);
        }
    }
}

// ---------------- host launcher ----------------
extern "C" void kernel_launch(void* const* d_in, const int* in_sizes, int n_in,
                              void* d_out, int out_size) {
    (void)in_sizes; (void)n_in; (void)out_size;
    const float* scores = (const float*)d_in[0];
    const float* deltas = (const float*)d_in[1];
    float* out = (float*)d_out;

    float *kin, *kout; int *vin, *vout, *off; void* tmp;
    cudaGetSymbolAddress((void**)&kin,  g_keys_in);
    cudaGetSymbolAddress((void**)&kout, g_keys_out);
    cudaGetSymbolAddress((void**)&vin,  g_vals_in);
    cudaGetSymbolAddress((void**)&vout, g_vals_out);
    cudaGetSymbolAddress((void**)&off,  g_seg_off);
    cudaGetSymbolAddress((void**)&tmp,  g_cub_temp);

    compute_props<<<(TOTAL + 255) / 256, 256>>>(scores, deltas);

    size_t temp_bytes = sizeof(g_cub_temp);
    cub::DeviceSegmentedRadixSort::SortPairsDescending(
        tmp, temp_bytes,
        kin, kout, vin, vout,
        TOTAL, BB, off, off + 1,
        0, 32, (cudaStream_t)0);

    gather_kernel<<<(BB * PRE_NMS + 255) / 256, 256>>>();

    const int mask_blocks = (PRE_NMS + MASK_ROWS_PER_BLOCK - 1) / MASK_ROWS_PER_BLOCK;
    mask_kernel<<<dim3(mask_blocks, BB), MASK_ROWS_PER_BLOCK>>>();

    resolve_kernel<<<BB, 32>>>(out);
}

// round 5
// speedup vs baseline: 2.9059x; 2.9059x over previous
#include <cuda_runtime.h>
#include <cuda_bf16.h>
#include <cub/cub.cuh>

// ---------------- problem constants ----------------
#define BB 4
#define AA 10
#define LL 4096
#define NPROP (LL * AA)          // 40960 per batch
#define TOTAL (BB * NPROP)       // 163840
#define PRE_NMS 6000
#define POST_NMS 300
#define NCHUNK ((PRE_NMS + 31) / 32)   // 188, last chunk has 16
#define NMS_THRESH_F 0.7f
#define MIN_SIZE_F 8.0f
#define FEAT_STRIDE 8
#define CLIP_MAX 32767.0f        // L*FEAT_STRIDE - 1
#define FULLMASK 0xFFFFFFFFu

// ---------------- static device scratch (no allocations allowed) ----------------
__device__ float g_x1[TOTAL];
__device__ float g_x2[TOTAL];
__device__ float g_keys_in[TOTAL];
__device__ float g_keys_out[TOTAL];
__device__ int   g_vals_in[TOTAL];
__device__ int   g_vals_out[TOTAL];
__device__ int   g_seg_off[BB + 1] = {0, NPROP, 2 * NPROP, 3 * NPROP, 4 * NPROP};
__device__ unsigned char g_cub_temp[8 << 20];
__device__ float2 g_obox[BB * PRE_NMS];    // sorted-order candidate boxes

__constant__ float c_scales[AA] = {2.f, 4.f, 5.f, 6.f, 8.f, 9.f, 10.f, 12.f, 14.f, 16.f};

// ---------------- kernel 1: decode proposals + scores (coalesced loads) ----------------
__global__ void compute_props(const float* __restrict__ scores_in,
                              const float* __restrict__ deltas_in) {
    int t = blockIdx.x * blockDim.x + threadIdx.x;
    if (t >= TOTAL) return;
    int l = t & (LL - 1);
    int ba = t >> 12;                  // b*AA + a
    int b = ba / AA;
    int a = ba - b * AA;

    const int base = b * (2 * AA) * LL;
    float score = scores_in[base + (AA + a) * LL + l];
    float d0    = deltas_in[base + (2 * a) * LL + l];
    float d1    = deltas_in[base + (2 * a + 1) * LL + l];

    float ws   = c_scales[a] * (float)FEAT_STRIDE;
    float ctrA = ((float)FEAT_STRIDE - 1.0f) * 0.5f;      // 3.5
    float shift = (float)(l * FEAT_STRIDE);
    float x1a = ctrA - 0.5f * (ws - 1.0f) + shift;
    float x2a = ctrA + 0.5f * (ws - 1.0f) + shift;

    float width = x2a - x1a + 1.0f;
    float ctr   = x1a + 0.5f * width;

    float pred_ctr = d0 * width + ctr;
    float pred_l   = expf(d1) * width;

    float x1 = pred_ctr - 0.5f * pred_l;
    float x2 = pred_ctr + 0.5f * pred_l;
    x1 = fminf(fmaxf(x1, 0.0f), CLIP_MAX);
    x2 = fminf(fmaxf(x2, 0.0f), CLIP_MAX);

    float ls = x2 - x1 + 1.0f;
    if (ls < MIN_SIZE_F) score = 0.0f;

    int r = l * AA + a;                // reference proposal index
    int idx = b * NPROP + r;
    g_x1[idx] = x1;
    g_x2[idx] = x2;
    g_keys_in[idx] = score;
    g_vals_in[idx] = r;
}

// ---------------- kernel 2: gather top-PRE_NMS boxes in sorted order ----------------
__global__ void gather_kernel() {
    int t = blockIdx.x * blockDim.x + threadIdx.x;
    if (t >= BB * PRE_NMS) return;
    int b = t / PRE_NMS;
    int i = t - b * PRE_NMS;
    int gi = b * NPROP + g_vals_out[b * NPROP + i];
    g_obox[t] = make_float2(g_x1[gi], g_x2[gi]);
}

// ---------------- kernel 3: chunked warp-parallel greedy NMS (1 warp / batch) --------
__global__ void nms_fused(float* __restrict__ out) {
    __shared__ float4 skept[POST_NMS];   // kept boxes: (x1, x2, len, pad)
    const int b = blockIdx.x;
    const int lane = threadIdx.x;        // 32 threads

    // init output rows [b, 0, 0]
    for (int i = lane; i < POST_NMS; i += 32) {
        float* o = out + (b * POST_NMS + i) * 3;
        o[0] = (float)b; o[1] = 0.0f; o[2] = 0.0f;
    }
    __syncwarp();

    const float2* __restrict__ obox = g_obox + b * PRE_NMS;

    // prefetch chunk 0
    float x1 = 0.f, x2 = -2.f;
    if (lane < PRE_NMS) { float2 t0 = obox[lane]; x1 = t0.x; x2 = t0.y; }

    int K = 0;
    for (int c = 0; c < NCHUNK; ++c) {
        const int i = c * 32 + lane;
        const bool valid = (i < PRE_NMS);
        const unsigned validMask = (c == NCHUNK - 1) ? 0xFFFFu : FULLMASK;

        // prefetch next chunk
        float nx1 = 0.f, nx2 = -2.f;
        {
            int ni = (c + 1) * 32 + lane;
            if (ni < PRE_NMS) { float2 tn = obox[ni]; nx1 = tn.x; nx2 = tn.y; }
        }

        const float len = x2 - x1 + 1.0f;

        // ---- phase 1: vs previously-kept list (broadcast LDS) ----
        bool sup = !valid;
        const int jmax = (K < POST_NMS) ? K : POST_NMS;
        for (int j = 0; j < jmax; ++j) {
            float4 kb = skept[j];                    // broadcast
            float inter = fminf(x2, kb.y) - fmaxf(x1, kb.x) + 1.0f;
            float uni = len + kb.z - inter;
            if (inter > 0.6999f * uni) {             // prefilter; decision by division
                if (inter / uni > NMS_THRESH_F) sup = true;
            }
        }

        // ---- phase 2: intra-chunk 32x32 pairwise rows via shfl butterfly ----
        unsigned row = 0u;
        #pragma unroll 4
        for (int d = 1; d < 32; ++d) {
            float ox1 = __shfl_xor_sync(FULLMASK, x1, d);
            float ox2 = __shfl_xor_sync(FULLMASK, x2, d);
            float olen = ox2 - ox1 + 1.0f;
            float inter = fminf(x2, ox2) - fmaxf(x1, ox1) + 1.0f;
            float uni = len + olen - inter;
            if (inter > 0.6999f * uni) {
                if (inter / uni > NMS_THRESH_F) row |= 1u << (lane ^ d);
            }
        }
        row &= validMask;

        // ---- phase 3: serial greedy resolution of the chunk (bit ops) ----
        unsigned removed = __ballot_sync(FULLMASK, sup) | ~validMask;
        unsigned keptbits = 0u;
        unsigned alive = ~removed;
        while (alive) {
            int p = __ffs(alive) - 1;                       // uniform across warp
            keptbits |= 1u << p;
            unsigned rowp = __shfl_sync(FULLMASK, row, p);  // row of kept candidate p
            removed |= rowp;
            alive = ~removed & ~((2u << p) - 1u);
        }

        // ---- phase 4: append kept to smem list + output ----
        int nk = __popc(keptbits);
        if (nk) {
            int myrank = K + __popc(keptbits & ((1u << lane) - 1u));
            if (((keptbits >> lane) & 1u) && myrank < POST_NMS) {
                skept[myrank] = make_float4(x1, x2, len, 0.0f);
                float* o = out + (b * POST_NMS + myrank) * 3;
                o[1] = x1; o[2] = x2;
            }
            K += nk;
            __syncwarp();
        }
        if (K >= POST_NMS) break;

        x1 = nx1; x2 = nx2;
    }
}

// ---------------- host launcher ----------------
extern "C" void kernel_launch(void* const* d_in, const int* in_sizes, int n_in,
                              void* d_out, int out_size) {
    (void)in_sizes; (void)n_in; (void)out_size;
    const float* scores = (const float*)d_in[0];
    const float* deltas = (const float*)d_in[1];
    float* out = (float*)d_out;

    float *kin, *kout; int *vin, *vout, *off; void* tmp;
    cudaGetSymbolAddress((void**)&kin,  g_keys_in);
    cudaGetSymbolAddress((void**)&kout, g_keys_out);
    cudaGetSymbolAddress((void**)&vin,  g_vals_in);
    cudaGetSymbolAddress((void**)&vout, g_vals_out);
    cudaGetSymbolAddress((void**)&off,  g_seg_off);
    cudaGetSymbolAddress((void**)&tmp,  g_cub_temp);

    compute_props<<<(TOTAL + 255) / 256, 256>>>(scores, deltas);

    size_t temp_bytes = sizeof(g_cub_temp);
    cub::DeviceSegmentedRadixSort::SortPairsDescending(
        tmp, temp_bytes,
        kin, kout, vin, vout,
        TOTAL, BB, off, off + 1,
        0, 32, (cudaStream_t)0);

    gather_kernel<<<(BB * PRE_NMS + 255) / 256, 256>>>();

    nms_fused<<<BB, 32>>>(out);
}

// round 6
// speedup vs baseline: 3.1716x; 1.0914x over previous
#include <cuda_runtime.h>
#include <cuda_bf16.h>
#include <cub/cub.cuh>

// ---------------- problem constants ----------------
#define BB 4
#define AA 10
#define LL 4096
#define NPROP (LL * AA)          // 40960 per batch
#define TOTAL (BB * NPROP)       // 163840
#define PRE_NMS 6000
#define POST_NMS 300
#define NCHUNK ((PRE_NMS + 31) / 32)   // 188
#define NMS_THRESH_F 0.7f
#define MIN_SIZE_F 8.0f
#define FEAT_STRIDE 8
#define CLIP_MAX 32767.0f        // L*FEAT_STRIDE - 1
#define FULLMASK 0xFFFFFFFFu
#define NMS_WARPS 8
#define NMS_THREADS (NMS_WARPS * 32)

// ---------------- static device scratch (no allocations allowed) ----------------
__device__ float g_x1[TOTAL];
__device__ float g_x2[TOTAL];
__device__ float g_keys_in[TOTAL];
__device__ float g_keys_out[TOTAL];
__device__ int   g_vals_in[TOTAL];
__device__ int   g_vals_out[TOTAL];
__device__ int   g_seg_off[BB + 1] = {0, NPROP, 2 * NPROP, 3 * NPROP, 4 * NPROP};
__device__ unsigned char g_cub_temp[8 << 20];

__constant__ float c_scales[AA] = {2.f, 4.f, 5.f, 6.f, 8.f, 9.f, 10.f, 12.f, 14.f, 16.f};

// ---------------- kernel 1: decode proposals + scores (coalesced loads) ----------------
__global__ void compute_props(const float* __restrict__ scores_in,
                              const float* __restrict__ deltas_in) {
    int t = blockIdx.x * blockDim.x + threadIdx.x;
    if (t >= TOTAL) return;
    int l = t & (LL - 1);
    int ba = t >> 12;                  // b*AA + a
    int b = ba / AA;
    int a = ba - b * AA;

    const int base = b * (2 * AA) * LL;
    float score = scores_in[base + (AA + a) * LL + l];
    float d0    = deltas_in[base + (2 * a) * LL + l];
    float d1    = deltas_in[base + (2 * a + 1) * LL + l];

    float ws   = c_scales[a] * (float)FEAT_STRIDE;
    float ctrA = ((float)FEAT_STRIDE - 1.0f) * 0.5f;      // 3.5
    float shift = (float)(l * FEAT_STRIDE);
    float x1a = ctrA - 0.5f * (ws - 1.0f) + shift;
    float x2a = ctrA + 0.5f * (ws - 1.0f) + shift;

    float width = x2a - x1a + 1.0f;
    float ctr   = x1a + 0.5f * width;

    float pred_ctr = d0 * width + ctr;
    float pred_l   = expf(d1) * width;

    float x1 = pred_ctr - 0.5f * pred_l;
    float x2 = pred_ctr + 0.5f * pred_l;
    x1 = fminf(fmaxf(x1, 0.0f), CLIP_MAX);
    x2 = fminf(fmaxf(x2, 0.0f), CLIP_MAX);

    float ls = x2 - x1 + 1.0f;
    if (ls < MIN_SIZE_F) score = 0.0f;

    int r = l * AA + a;                // reference proposal index
    int idx = b * NPROP + r;
    g_x1[idx] = x1;
    g_x2[idx] = x2;
    g_keys_in[idx] = score;
    g_vals_in[idx] = r;
}

// ---------------- kernel 2: fused gather + multi-warp greedy NMS (1 block / batch) ----
// dynamic smem: scand[PRE_NMS] float2 (48000 B) + skept[POST_NMS] float4 (4800 B)
__global__ void nms_fused(float* __restrict__ out) {
    extern __shared__ unsigned char smem_raw[];
    float2* scand = (float2*)smem_raw;
    float4* skept = (float4*)(scand + PRE_NMS);
    __shared__ unsigned s_sup[NMS_WARPS];
    __shared__ int s_K;

    const int b    = blockIdx.x;
    const int tid  = threadIdx.x;
    const int wid  = tid >> 5;
    const int lane = tid & 31;

    // gather top-PRE_NMS boxes (sorted order) into shared; init output
    const int* __restrict__ vals = g_vals_out + b * NPROP;
    for (int i = tid; i < PRE_NMS; i += NMS_THREADS) {
        int gi = b * NPROP + vals[i];
        scand[i] = make_float2(g_x1[gi], g_x2[gi]);
    }
    for (int i = tid; i < POST_NMS; i += NMS_THREADS) {
        float* o = out + (b * POST_NMS + i) * 3;
        o[0] = (float)b; o[1] = 0.0f; o[2] = 0.0f;
    }
    if (tid == 0) s_K = 0;
    __syncthreads();

    for (int c = 0; c < NCHUNK; ++c) {
        const int i = c * 32 + lane;
        const bool valid = (i < PRE_NMS);
        const int nvalid = PRE_NMS - c * 32;
        const unsigned validMask =
            (nvalid >= 32) ? FULLMASK : ((1u << nvalid) - 1u);

        float x1 = 0.0f, x2 = -2.0f;
        if (valid) { float2 t0 = scand[i]; x1 = t0.x; x2 = t0.y; }
        const float len = x2 - x1 + 1.0f;
        const int K = s_K;

        // ---- phase 1 (8 warps): candidate vs kept list, j strided by warp ----
        bool sup = !valid;
        for (int j = wid; j < K; j += NMS_WARPS) {
            float4 kb = skept[j];                    // broadcast within warp
            float inter = fminf(x2, kb.y) - fmaxf(x1, kb.x) + 1.0f;
            float uni = len + kb.z - inter;
            if (inter > 0.6999f * uni) {             // prefilter; decision by division
                if (inter / uni > NMS_THRESH_F) sup = true;
            }
            if (__all_sync(FULLMASK, sup)) break;
        }
        {
            unsigned bal = __ballot_sync(FULLMASK, sup);
            if (lane == 0) s_sup[wid] = bal;
        }
        __syncthreads();

        // ---- phases 2-4 (warp 0 only) ----
        if (wid == 0) {
            unsigned removed = ~validMask;
            #pragma unroll
            for (int w = 0; w < NMS_WARPS; ++w) removed |= s_sup[w];

            // intra-chunk 32x32 pairwise rows via shfl butterfly
            unsigned row = 0u;
            #pragma unroll 4
            for (int d = 1; d < 32; ++d) {
                float ox1 = __shfl_xor_sync(FULLMASK, x1, d);
                float ox2 = __shfl_xor_sync(FULLMASK, x2, d);
                float olen = ox2 - ox1 + 1.0f;
                float inter = fminf(x2, ox2) - fmaxf(x1, ox1) + 1.0f;
                float uni = len + olen - inter;
                if (inter > 0.6999f * uni) {
                    if (inter / uni > NMS_THRESH_F) row |= 1u << (lane ^ d);
                }
            }
            row &= validMask;

            // serial greedy resolution of the chunk
            unsigned keptbits = 0u;
            unsigned alive = ~removed;
            while (alive) {
                int p = __ffs(alive) - 1;                       // uniform
                keptbits |= 1u << p;
                unsigned rowp = __shfl_sync(FULLMASK, row, p);
                removed |= rowp;
                alive = ~removed & ~((2u << p) - 1u);
            }

            // append kept boxes
            int nk = __popc(keptbits);
            if (nk) {
                int myrank = K + __popc(keptbits & ((1u << lane) - 1u));
                if (((keptbits >> lane) & 1u) && myrank < POST_NMS) {
                    skept[myrank] = make_float4(x1, x2, len, 0.0f);
                    float* o = out + (b * POST_NMS + myrank) * 3;
                    o[1] = x1; o[2] = x2;
                }
                if (lane == 0) s_K = K + nk;
            }
        }
        __syncthreads();
        if (s_K >= POST_NMS) break;
    }
}

// ---------------- host launcher ----------------
extern "C" void kernel_launch(void* const* d_in, const int* in_sizes, int n_in,
                              void* d_out, int out_size) {
    (void)in_sizes; (void)n_in; (void)out_size;
    const float* scores = (const float*)d_in[0];
    const float* deltas = (const float*)d_in[1];
    float* out = (float*)d_out;

    float *kin, *kout; int *vin, *vout, *off; void* tmp;
    cudaGetSymbolAddress((void**)&kin,  g_keys_in);
    cudaGetSymbolAddress((void**)&kout, g_keys_out);
    cudaGetSymbolAddress((void**)&vin,  g_vals_in);
    cudaGetSymbolAddress((void**)&vout, g_vals_out);
    cudaGetSymbolAddress((void**)&off,  g_seg_off);
    cudaGetSymbolAddress((void**)&tmp,  g_cub_temp);

    compute_props<<<(TOTAL + 255) / 256, 256>>>(scores, deltas);

    size_t temp_bytes = sizeof(g_cub_temp);
    cub::DeviceSegmentedRadixSort::SortPairsDescending(
        tmp, temp_bytes,
        kin, kout, vin, vout,
        TOTAL, BB, off, off + 1,
        0, 32, (cudaStream_t)0);

    const int smem_bytes = PRE_NMS * (int)sizeof(float2) + POST_NMS * (int)sizeof(float4);
    cudaFuncSetAttribute(nms_fused, cudaFuncAttributeMaxDynamicSharedMemorySize, smem_bytes);
    nms_fused<<<BB, NMS_THREADS, smem_bytes>>>(out);
}

// round 7
// speedup vs baseline: 7.3030x; 2.3026x over previous
#include <cuda_runtime.h>
#include <cuda_bf16.h>
#include <cub/cub.cuh>

// ---------------- problem constants ----------------
#define BB 4
#define AA 10
#define LL 4096
#define NPROP (LL * AA)          // 40960 per batch (fits in 16 bits)
#define TOTAL (BB * NPROP)       // 163840
#define PRE_NMS 6000
#define POST_NMS 300
#define NCHUNK ((PRE_NMS + 31) / 32)   // 188
#define NMS_THRESH_F 0.7f
#define MIN_SIZE_F 8.0f
#define FEAT_STRIDE 8
#define CLIP_MAX 32767.0f        // L*FEAT_STRIDE - 1
#define FULLMASK 0xFFFFFFFFu
#define NMS_WARPS 8
#define NMS_THREADS (NMS_WARPS * 32)

// ---------------- static device scratch (no allocations allowed) ----------------
__device__ float g_x1[TOTAL];
__device__ float g_x2[TOTAL];
__device__ unsigned long long g_ckey_in[TOTAL];
__device__ unsigned long long g_ckey_out[TOTAL];
__device__ unsigned char g_cub_temp[8 << 20];

__constant__ float c_scales[AA] = {2.f, 4.f, 5.f, 6.f, 8.f, 9.f, 10.f, 12.f, 14.f, 16.f};

// ---------------- kernel 1: decode proposals + build composite sort keys ----------------
// ckey = (b << 48) | ((~orderable(score)) << 16) | r
// ascending sort => batch-major, score-descending, index-ascending on ties.
__global__ void compute_props(const float* __restrict__ scores_in,
                              const float* __restrict__ deltas_in) {
    int t = blockIdx.x * blockDim.x + threadIdx.x;
    if (t >= TOTAL) return;
    int l = t & (LL - 1);
    int ba = t >> 12;                  // b*AA + a
    int b = ba / AA;
    int a = ba - b * AA;

    const int base = b * (2 * AA) * LL;
    float score = scores_in[base + (AA + a) * LL + l];
    float d0    = deltas_in[base + (2 * a) * LL + l];
    float d1    = deltas_in[base + (2 * a + 1) * LL + l];

    float ws   = c_scales[a] * (float)FEAT_STRIDE;
    float ctrA = ((float)FEAT_STRIDE - 1.0f) * 0.5f;      // 3.5
    float shift = (float)(l * FEAT_STRIDE);
    float x1a = ctrA - 0.5f * (ws - 1.0f) + shift;
    float x2a = ctrA + 0.5f * (ws - 1.0f) + shift;

    float width = x2a - x1a + 1.0f;
    float ctr   = x1a + 0.5f * width;

    float pred_ctr = d0 * width + ctr;
    float pred_l   = expf(d1) * width;

    float x1 = pred_ctr - 0.5f * pred_l;
    float x2 = pred_ctr + 0.5f * pred_l;
    x1 = fminf(fmaxf(x1, 0.0f), CLIP_MAX);
    x2 = fminf(fmaxf(x2, 0.0f), CLIP_MAX);

    float ls = x2 - x1 + 1.0f;
    if (ls < MIN_SIZE_F) score = 0.0f;

    int r = l * AA + a;                // reference proposal index within batch
    int idx = b * NPROP + r;
    g_x1[idx] = x1;
    g_x2[idx] = x2;

    // monotone float -> uint mapping (ascending float -> ascending key)
    unsigned u = __float_as_uint(score);
    unsigned skey = (u & 0x80000000u) ? ~u : (u | 0x80000000u);
    unsigned long long ckey = ((unsigned long long)b << 48)
                            | ((unsigned long long)(~skey) << 16)
                            | (unsigned)r;
    g_ckey_in[idx] = ckey;
}

// ---------------- kernel 2: fused gather + multi-warp greedy NMS (1 block / batch) ----
// dynamic smem: scand[PRE_NMS] float2 (48000 B) + skept[POST_NMS] float4 (4800 B)
__global__ void nms_fused(float* __restrict__ out) {
    extern __shared__ unsigned char smem_raw[];
    float2* scand = (float2*)smem_raw;
    float4* skept = (float4*)(scand + PRE_NMS);
    __shared__ unsigned s_sup[NMS_WARPS];
    __shared__ int s_K;

    const int b    = blockIdx.x;
    const int tid  = threadIdx.x;
    const int wid  = tid >> 5;
    const int lane = tid & 31;

    // gather top-PRE_NMS boxes (sorted order) into shared; init output
    const unsigned long long* __restrict__ skeys = g_ckey_out + b * NPROP;
    for (int i = tid; i < PRE_NMS; i += NMS_THREADS) {
        int r = (int)(skeys[i] & 0xFFFFu);
        int gi = b * NPROP + r;
        scand[i] = make_float2(g_x1[gi], g_x2[gi]);
    }
    for (int i = tid; i < POST_NMS; i += NMS_THREADS) {
        float* o = out + (b * POST_NMS + i) * 3;
        o[0] = (float)b; o[1] = 0.0f; o[2] = 0.0f;
    }
    if (tid == 0) s_K = 0;
    __syncthreads();

    for (int c = 0; c < NCHUNK; ++c) {
        const int i = c * 32 + lane;
        const bool valid = (i < PRE_NMS);
        const int nvalid = PRE_NMS - c * 32;
        const unsigned validMask =
            (nvalid >= 32) ? FULLMASK : ((1u << nvalid) - 1u);

        float x1 = 0.0f, x2 = -2.0f;
        if (valid) { float2 t0 = scand[i]; x1 = t0.x; x2 = t0.y; }
        const float len = x2 - x1 + 1.0f;
        const int K = s_K;

        // ---- phase 1 (8 warps): candidate vs kept list, j strided by warp ----
        bool sup = !valid;
        for (int j = wid; j < K; j += NMS_WARPS) {
            float4 kb = skept[j];                    // broadcast within warp
            float inter = fminf(x2, kb.y) - fmaxf(x1, kb.x) + 1.0f;
            float uni = len + kb.z - inter;
            if (inter > 0.6999f * uni) {             // prefilter; decision by division
                if (inter / uni > NMS_THRESH_F) sup = true;
            }
            if (__all_sync(FULLMASK, sup)) break;
        }
        {
            unsigned bal = __ballot_sync(FULLMASK, sup);
            if (lane == 0) s_sup[wid] = bal;
        }
        __syncthreads();

        // ---- phases 2-4 (warp 0 only) ----
        if (wid == 0) {
            unsigned removed = ~validMask;
            #pragma unroll
            for (int w = 0; w < NMS_WARPS; ++w) removed |= s_sup[w];

            // intra-chunk 32x32 pairwise rows via shfl butterfly
            unsigned row = 0u;
            #pragma unroll 4
            for (int d = 1; d < 32; ++d) {
                float ox1 = __shfl_xor_sync(FULLMASK, x1, d);
                float ox2 = __shfl_xor_sync(FULLMASK, x2, d);
                float olen = ox2 - ox1 + 1.0f;
                float inter = fminf(x2, ox2) - fmaxf(x1, ox1) + 1.0f;
                float uni = len + olen - inter;
                if (inter > 0.6999f * uni) {
                    if (inter / uni > NMS_THRESH_F) row |= 1u << (lane ^ d);
                }
            }
            row &= validMask;

            // serial greedy resolution of the chunk
            unsigned keptbits = 0u;
            unsigned alive = ~removed;
            while (alive) {
                int p = __ffs(alive) - 1;                       // uniform
                keptbits |= 1u << p;
                unsigned rowp = __shfl_sync(FULLMASK, row, p);
                removed |= rowp;
                alive = ~removed & ~((2u << p) - 1u);
            }

            // append kept boxes
            int nk = __popc(keptbits);
            if (nk) {
                int myrank = K + __popc(keptbits & ((1u << lane) - 1u));
                if (((keptbits >> lane) & 1u) && myrank < POST_NMS) {
                    skept[myrank] = make_float4(x1, x2, len, 0.0f);
                    float* o = out + (b * POST_NMS + myrank) * 3;
                    o[1] = x1; o[2] = x2;
                }
                if (lane == 0) s_K = K + nk;
            }
        }
        __syncthreads();
        if (s_K >= POST_NMS) break;
    }
}

// ---------------- host launcher ----------------
extern "C" void kernel_launch(void* const* d_in, const int* in_sizes, int n_in,
                              void* d_out, int out_size) {
    (void)in_sizes; (void)n_in; (void)out_size;
    const float* scores = (const float*)d_in[0];
    const float* deltas = (const float*)d_in[1];
    float* out = (float*)d_out;

    unsigned long long *kin, *kout; void* tmp;
    cudaGetSymbolAddress((void**)&kin,  g_ckey_in);
    cudaGetSymbolAddress((void**)&kout, g_ckey_out);
    cudaGetSymbolAddress((void**)&tmp,  g_cub_temp);

    compute_props<<<(TOTAL + 255) / 256, 256>>>(scores, deltas);

    // single full-device keys-only radix sort on 50-bit composite keys
    size_t temp_bytes = sizeof(g_cub_temp);
    cub::DeviceRadixSort::SortKeys(
        tmp, temp_bytes,
        kin, kout, TOTAL,
        0, 50, (cudaStream_t)0);

    const int smem_bytes = PRE_NMS * (int)sizeof(float2) + POST_NMS * (int)sizeof(float4);
    cudaFuncSetAttribute(nms_fused, cudaFuncAttributeMaxDynamicSharedMemorySize, smem_bytes);
    nms_fused<<<BB, NMS_THREADS, smem_bytes>>>(out);
}

// round 8
// speedup vs baseline: 8.8078x; 1.2060x over previous
#include <cuda_runtime.h>
#include <cuda_bf16.h>
#include <cub/cub.cuh>

// ---------------- problem constants ----------------
#define BB 4
#define AA 10
#define LL 4096
#define NPROP (LL * AA)          // 40960 per batch (fits in 16 bits)
#define TOTAL (BB * NPROP)       // 163840
#define PRE_NMS 6000
#define POST_NMS 300
#define NCHUNK ((PRE_NMS + 31) / 32)   // 188
#define NMS_THRESH_F 0.7f
#define MIN_SIZE_F 8.0f
#define FEAT_STRIDE 8
#define CLIP_MAX 32767.0f        // L*FEAT_STRIDE - 1
#define FULLMASK 0xFFFFFFFFu
#define NMS_WARPS 8
#define NMS_THREADS (NMS_WARPS * 32)

// ---------------- static device scratch (no allocations allowed) ----------------
__device__ float g_x1[TOTAL];
__device__ float g_x2[TOTAL];
__device__ unsigned long long g_ckey_in[TOTAL];
__device__ unsigned long long g_ckey_out[TOTAL];
__device__ unsigned char g_cub_temp[8 << 20];

__constant__ float c_scales[AA] = {2.f, 4.f, 5.f, 6.f, 8.f, 9.f, 10.f, 12.f, 14.f, 16.f};

// ---------------- kernel 1: decode proposals + build composite sort keys ----------------
// ckey = (b << 48) | ((~orderable(score)) << 16) | r
// Radix-sorting bits [16,50) ascending => batch-major, score-descending.
// Ties (same batch+score) keep INPUT order (onesweep is stable), and input is
// written at idx = b*NPROP + r => r-ascending, matching the reference argsort.
__global__ void compute_props(const float* __restrict__ scores_in,
                              const float* __restrict__ deltas_in) {
    int t = blockIdx.x * blockDim.x + threadIdx.x;
    if (t >= TOTAL) return;
    int l = t & (LL - 1);
    int ba = t >> 12;                  // b*AA + a
    int b = ba / AA;
    int a = ba - b * AA;

    const int base = b * (2 * AA) * LL;
    float score = scores_in[base + (AA + a) * LL + l];
    float d0    = deltas_in[base + (2 * a) * LL + l];
    float d1    = deltas_in[base + (2 * a + 1) * LL + l];

    float ws   = c_scales[a] * (float)FEAT_STRIDE;
    float ctrA = ((float)FEAT_STRIDE - 1.0f) * 0.5f;      // 3.5
    float shift = (float)(l * FEAT_STRIDE);
    float x1a = ctrA - 0.5f * (ws - 1.0f) + shift;
    float x2a = ctrA + 0.5f * (ws - 1.0f) + shift;

    float width = x2a - x1a + 1.0f;
    float ctr   = x1a + 0.5f * width;

    float pred_ctr = d0 * width + ctr;
    float pred_l   = expf(d1) * width;

    float x1 = pred_ctr - 0.5f * pred_l;
    float x2 = pred_ctr + 0.5f * pred_l;
    x1 = fminf(fmaxf(x1, 0.0f), CLIP_MAX);
    x2 = fminf(fmaxf(x2, 0.0f), CLIP_MAX);

    float ls = x2 - x1 + 1.0f;
    if (ls < MIN_SIZE_F) score = 0.0f;

    int r = l * AA + a;                // reference proposal index within batch
    int idx = b * NPROP + r;
    g_x1[idx] = x1;
    g_x2[idx] = x2;

    // monotone float -> uint mapping (ascending float -> ascending key)
    unsigned u = __float_as_uint(score);
    unsigned skey = (u & 0x80000000u) ? ~u : (u | 0x80000000u);
    unsigned long long ckey = ((unsigned long long)b << 48)
                            | ((unsigned long long)(~skey) << 16)
                            | (unsigned)r;
    g_ckey_in[idx] = ckey;
}

// ---------------- kernel 2: fused gather + multi-warp greedy NMS (1 block / batch) ----
// dynamic smem: scand[PRE_NMS] float2 (48000 B) + skept[POST_NMS] float4 (4800 B)
__global__ void nms_fused(float* __restrict__ out) {
    extern __shared__ unsigned char smem_raw[];
    float2* scand = (float2*)smem_raw;
    float4* skept = (float4*)(scand + PRE_NMS);
    __shared__ unsigned s_sup[NMS_WARPS];
    __shared__ unsigned s_rowp[NMS_WARPS][32];
    __shared__ int s_K;

    const int b    = blockIdx.x;
    const int tid  = threadIdx.x;
    const int wid  = tid >> 5;
    const int lane = tid & 31;

    // gather top-PRE_NMS boxes (sorted order) into shared; init output
    const unsigned long long* __restrict__ skeys = g_ckey_out + b * NPROP;
    for (int i = tid; i < PRE_NMS; i += NMS_THREADS) {
        int r = (int)(skeys[i] & 0xFFFFu);
        int gi = b * NPROP + r;
        scand[i] = make_float2(g_x1[gi], g_x2[gi]);
    }
    for (int i = tid; i < POST_NMS; i += NMS_THREADS) {
        float* o = out + (b * POST_NMS + i) * 3;
        o[0] = (float)b; o[1] = 0.0f; o[2] = 0.0f;
    }
    if (tid == 0) s_K = 0;
    __syncthreads();

    for (int c = 0; c < NCHUNK; ++c) {
        const int i = c * 32 + lane;
        const bool valid = (i < PRE_NMS);
        const int nvalid = PRE_NMS - c * 32;
        const unsigned validMask =
            (nvalid >= 32) ? FULLMASK : ((1u << nvalid) - 1u);

        float x1 = 0.0f, x2 = -2.0f;
        if (valid) { float2 t0 = scand[i]; x1 = t0.x; x2 = t0.y; }
        const float len = x2 - x1 + 1.0f;
        const int K = s_K;

        // ---- phase 1 (all 8 warps): candidate vs kept list, j strided by warp ----
        bool sup = !valid;
        int it = 0;
        for (int j = wid; j < K; j += NMS_WARPS) {
            float4 kb = skept[j];                    // broadcast within warp
            float inter = fminf(x2, kb.y) - fmaxf(x1, kb.x) + 1.0f;
            float uni = len + kb.z - inter;
            if (inter > 0.6999f * uni) {             // prefilter; decision by division
                if (inter / uni > NMS_THRESH_F) sup = true;
            }
            if (((++it) & 3) == 0 && __all_sync(FULLMASK, sup)) break;
        }
        {
            unsigned bal = __ballot_sync(FULLMASK, sup);
            if (lane == 0) s_sup[wid] = bal;
        }

        // ---- phase 2 (all 8 warps): split intra-chunk butterfly, <=4 offsets each ----
        {
            unsigned rowp = 0u;
            const int d0 = 4 * wid + 1;
            const int d1 = (4 * wid + 4 < 32) ? 4 * wid + 4 : 31;
            for (int d = d0; d <= d1; ++d) {
                float ox1 = __shfl_xor_sync(FULLMASK, x1, d);
                float ox2 = __shfl_xor_sync(FULLMASK, x2, d);
                float olen = ox2 - ox1 + 1.0f;
                float inter = fminf(x2, ox2) - fmaxf(x1, ox1) + 1.0f;
                float uni = len + olen - inter;
                if (inter > 0.6999f * uni) {
                    if (inter / uni > NMS_THRESH_F) rowp |= 1u << (lane ^ d);
                }
            }
            s_rowp[wid][lane] = rowp;
        }
        __syncthreads();

        // ---- phases 3-4 (warp 0 only): resolve + append ----
        if (wid == 0) {
            unsigned removed = ~validMask;
            #pragma unroll
            for (int w = 0; w < NMS_WARPS; ++w) removed |= s_sup[w];

            unsigned row = 0u;
            #pragma unroll
            for (int w = 0; w < NMS_WARPS; ++w) row |= s_rowp[w][lane];
            row &= validMask;

            // serial greedy resolution of the chunk
            unsigned keptbits = 0u;
            unsigned alive = ~removed;
            while (alive) {
                int p = __ffs(alive) - 1;                       // uniform
                keptbits |= 1u << p;
                unsigned rowp = __shfl_sync(FULLMASK, row, p);
                removed |= rowp;
                alive = ~removed & ~((2u << p) - 1u);
            }

            // append kept boxes
            int nk = __popc(keptbits);
            if (nk) {
                int myrank = K + __popc(keptbits & ((1u << lane) - 1u));
                if (((keptbits >> lane) & 1u) && myrank < POST_NMS) {
                    skept[myrank] = make_float4(x1, x2, len, 0.0f);
                    float* o = out + (b * POST_NMS + myrank) * 3;
                    o[1] = x1; o[2] = x2;
                }
                if (lane == 0) s_K = K + nk;
            }
        }
        __syncthreads();
        if (s_K >= POST_NMS) break;
    }
}

// ---------------- host launcher ----------------
extern "C" void kernel_launch(void* const* d_in, const int* in_sizes, int n_in,
                              void* d_out, int out_size) {
    (void)in_sizes; (void)n_in; (void)out_size;
    const float* scores = (const float*)d_in[0];
    const float* deltas = (const float*)d_in[1];
    float* out = (float*)d_out;

    unsigned long long *kin, *kout; void* tmp;
    cudaGetSymbolAddress((void**)&kin,  g_ckey_in);
    cudaGetSymbolAddress((void**)&kout, g_ckey_out);
    cudaGetSymbolAddress((void**)&tmp,  g_cub_temp);

    compute_props<<<(TOTAL + 255) / 256, 256>>>(scores, deltas);

    // full-device keys-only radix sort; bits [16,50) only (stability supplies the
    // r-ascending tie-break from input order) -> 5 onesweep passes instead of 7
    size_t temp_bytes = sizeof(g_cub_temp);
    cub::DeviceRadixSort::SortKeys(
        tmp, temp_bytes,
        kin, kout, TOTAL,
        16, 50, (cudaStream_t)0);

    const int smem_bytes = PRE_NMS * (int)sizeof(float2) + POST_NMS * (int)sizeof(float4);
    cudaFuncSetAttribute(nms_fused, cudaFuncAttributeMaxDynamicSharedMemorySize, smem_bytes);
    nms_fused<<<BB, NMS_THREADS, smem_bytes>>>(out);
}